// round 1
// baseline (speedup 1.0000x reference)
#include <cuda_runtime.h>
#include <math.h>

#define B_    8
#define LQ_   2048
#define LK_   1024
#define QIN   1124
#define KIN   10100
#define PROJ_ 500
#define HEADS 10
#define HD    50

// Scratch (allocation-free): projected q, projected k, attention output
__device__ float g_q[B_ * LQ_ * PROJ_];      // 16384 x 500
__device__ float g_k[B_ * LK_ * PROJ_];      // 8192  x 500
__device__ float g_attn[B_ * LQ_ * HEADS];   // 16384 x 10

// ---------------------------------------------------------------------------
// SGEMM: C[M,N] = A[M,K] @ W[K,N] + bias[N]
// 128x128 block tile, BK=8, 16x16 threads, 8x8 per-thread frag.
// Thread columns are strided (tx + 16*j) for conflict-free Bs reads.
// M must be a multiple of 128 (true here); N,K guarded.
// ---------------------------------------------------------------------------
__global__ __launch_bounds__(256) void sgemm_bias(
    const float* __restrict__ A, const float* __restrict__ W,
    const float* __restrict__ bias, float* __restrict__ C,
    int M, int N, int K)
{
    __shared__ float As[8][128];
    __shared__ float Bs[8][128];

    const int t  = threadIdx.x;
    const int tx = t & 15;
    const int ty = t >> 4;
    const int m0 = blockIdx.y * 128;
    const int n0 = blockIdx.x * 128;

    float acc[8][8];
#pragma unroll
    for (int i = 0; i < 8; i++)
#pragma unroll
        for (int j = 0; j < 8; j++) acc[i][j] = 0.0f;

    for (int k0 = 0; k0 < K; k0 += 8) {
        // Load A tile (128 rows x 8 k), transposed into As[k][row]
#pragma unroll
        for (int i = 0; i < 4; i++) {
            int idx = t + i * 256;
            int r = idx >> 3;
            int c = idx & 7;
            float v = 0.0f;
            if (k0 + c < K) v = A[(size_t)(m0 + r) * K + k0 + c];
            As[c][r] = v;
        }
        // Load W tile (8 k x 128 n)
#pragma unroll
        for (int i = 0; i < 4; i++) {
            int idx = t + i * 256;
            int r = idx >> 7;
            int c = idx & 127;
            float v = 0.0f;
            if ((k0 + r < K) && (n0 + c < N)) v = W[(size_t)(k0 + r) * N + n0 + c];
            Bs[r][c] = v;
        }
        __syncthreads();

#pragma unroll
        for (int kk = 0; kk < 8; kk++) {
            float a[8], b[8];
#pragma unroll
            for (int i = 0; i < 8; i++) a[i] = As[kk][ty * 8 + i];
#pragma unroll
            for (int j = 0; j < 8; j++) b[j] = Bs[kk][tx + 16 * j];
#pragma unroll
            for (int i = 0; i < 8; i++)
#pragma unroll
                for (int j = 0; j < 8; j++) acc[i][j] += a[i] * b[j];
        }
        __syncthreads();
    }

#pragma unroll
    for (int i = 0; i < 8; i++) {
        int m = m0 + ty * 8 + i;
#pragma unroll
        for (int j = 0; j < 8; j++) {
            int n = n0 + tx + 16 * j;
            if (n < N) C[(size_t)m * N + n] = acc[i][j] + bias[n];
        }
    }
}

// ---------------------------------------------------------------------------
// Fused attention: per block (b, h, 128-q tile).
// Streams k in 128-row tiles; per-thread 8x8 score frag; no max-subtraction
// (scores are O(1) for this data), accumulates sum(e*v) and sum(e).
// Dynamic smem: qs[128*50] + ks[128*50] + vsh[128] = 51,712 B.
// ---------------------------------------------------------------------------
__global__ __launch_bounds__(256) void attn_kernel(const float* __restrict__ value)
{
    extern __shared__ float sm[];
    float* qs  = sm;            // 6400 floats
    float* ks  = sm + 6400;     // 6400 floats
    float* vsh = sm + 12800;    // 128  floats

    const int b  = blockIdx.z;
    const int h  = blockIdx.y;
    const int q0 = blockIdx.x * 128;
    const int t  = threadIdx.x;
    const int tx = t & 15;
    const int ty = t >> 4;

    // Load q tile: rows q0..q0+127, dims h*50..h*50+49
    for (int idx = t; idx < 128 * HD; idx += 256) {
        int r = idx / HD;
        int c = idx - r * HD;
        qs[idx] = g_q[(size_t)(b * LQ_ + q0 + r) * PROJ_ + h * HD + c];
    }

    float accA[8], accL[8];
#pragma unroll
    for (int i = 0; i < 8; i++) { accA[i] = 0.0f; accL[i] = 0.0f; }

    const float scale = 0.14142135623730951f; // 1/sqrt(50)

    for (int kt = 0; kt < LK_; kt += 128) {
        __syncthreads();   // protect ks/vsh from previous iteration's readers
        for (int idx = t; idx < 128 * HD; idx += 256) {
            int r = idx / HD;
            int c = idx - r * HD;
            ks[idx] = g_k[(size_t)(b * LK_ + kt + r) * PROJ_ + h * HD + c];
        }
        if (t < 128) vsh[t] = value[b * LK_ + kt + t];
        __syncthreads();

        float s[8][8];
#pragma unroll
        for (int i = 0; i < 8; i++)
#pragma unroll
            for (int j = 0; j < 8; j++) s[i][j] = 0.0f;

#pragma unroll
        for (int d = 0; d < HD; d += 2) {
            float2 a[8], bb[8];
#pragma unroll
            for (int i = 0; i < 8; i++)
                a[i] = *(const float2*)&qs[(ty * 8 + i) * HD + d];
#pragma unroll
            for (int j = 0; j < 8; j++)
                bb[j] = *(const float2*)&ks[(tx + 16 * j) * HD + d];
#pragma unroll
            for (int i = 0; i < 8; i++)
#pragma unroll
                for (int j = 0; j < 8; j++) {
                    s[i][j] += a[i].x * bb[j].x;
                    s[i][j] += a[i].y * bb[j].y;
                }
        }

#pragma unroll
        for (int j = 0; j < 8; j++) {
            float v = vsh[tx + 16 * j];
#pragma unroll
            for (int i = 0; i < 8; i++) {
                float e = __expf(s[i][j] * scale);
                accA[i] += e * v;
                accL[i] += e;
            }
        }
    }

    // Reduce across the 16 tx lanes (xor 8,4,2,1 stays inside a 16-lane group)
#pragma unroll
    for (int i = 0; i < 8; i++) {
        float a = accA[i];
        float l = accL[i];
#pragma unroll
        for (int o = 8; o > 0; o >>= 1) {
            a += __shfl_xor_sync(0xffffffffu, a, o);
            l += __shfl_xor_sync(0xffffffffu, l, o);
        }
        if (tx == 0)
            g_attn[(size_t)(b * LQ_ + q0 + ty * 8 + i) * HEADS + h] = a / l;
    }
}

// ---------------------------------------------------------------------------
// Tiny MLP: y = relu(relu(o @ W1 + b1) @ W2 + b2)
// ---------------------------------------------------------------------------
__global__ __launch_bounds__(256) void mlp_kernel(
    const float* __restrict__ W1, const float* __restrict__ b1,
    const float* __restrict__ W2, const float* __restrict__ b2,
    float* __restrict__ out)
{
    int idx = blockIdx.x * blockDim.x + threadIdx.x;
    if (idx >= B_ * LQ_) return;

    float o[HEADS];
#pragma unroll
    for (int i = 0; i < HEADS; i++) o[i] = g_attn[(size_t)idx * HEADS + i];

    float y = b2[0];
#pragma unroll
    for (int j = 0; j < 10; j++) {
        float hj = b1[j];
#pragma unroll
        for (int i = 0; i < HEADS; i++) hj += o[i] * W1[i * 10 + j];
        hj = fmaxf(hj, 0.0f);
        y += hj * W2[j];
    }
    out[idx] = fmaxf(y, 0.0f);
}

// ---------------------------------------------------------------------------
extern "C" void kernel_launch(void* const* d_in, const int* in_sizes, int n_in,
                              void* d_out, int out_size)
{
    const float* query = (const float*)d_in[0];
    const float* key   = (const float*)d_in[1];
    const float* value = (const float*)d_in[2];
    const float* Wq    = (const float*)d_in[3];
    const float* bq    = (const float*)d_in[4];
    const float* Wk    = (const float*)d_in[5];
    const float* bk    = (const float*)d_in[6];
    const float* W1    = (const float*)d_in[7];
    const float* b1    = (const float*)d_in[8];
    const float* W2    = (const float*)d_in[9];
    const float* b2    = (const float*)d_in[10];
    float* out = (float*)d_out;

    float *gq = nullptr, *gk = nullptr;
    cudaGetSymbolAddress((void**)&gq, g_q);
    cudaGetSymbolAddress((void**)&gk, g_k);

    // q projection: [16384,1124] @ [1124,500]
    {
        dim3 grid((PROJ_ + 127) / 128, (B_ * LQ_) / 128);
        sgemm_bias<<<grid, 256>>>(query, Wq, bq, gq, B_ * LQ_, PROJ_, QIN);
    }
    // k projection: [8192,10100] @ [10100,500]
    {
        dim3 grid((PROJ_ + 127) / 128, (B_ * LK_) / 128);
        sgemm_bias<<<grid, 256>>>(key, Wk, bk, gk, B_ * LK_, PROJ_, KIN);
    }
    // fused attention
    {
        const int smem = (128 * HD + 128 * HD + 128) * (int)sizeof(float); // 51,712 B
        cudaFuncSetAttribute(attn_kernel,
                             cudaFuncAttributeMaxDynamicSharedMemorySize, smem);
        dim3 grid(LQ_ / 128, HEADS, B_);
        attn_kernel<<<grid, 256, smem>>>(value);
    }
    // MLP head
    {
        int n = B_ * LQ_;
        mlp_kernel<<<(n + 255) / 256, 256>>>(W1, b1, W2, b2, out);
    }
}

// round 2
// speedup vs baseline: 1.2479x; 1.2479x over previous
#include <cuda_runtime.h>
#include <math.h>

#define B_    8
#define LQ_   2048
#define LK_   1024
#define QIN   1124
#define KIN   10100
#define PROJ_ 500
#define HEADS 10
#define HD    50

// Scratch (allocation-free): projected q, projected k, attention output
__device__ float g_q[B_ * LQ_ * PROJ_];      // 16384 x 500
__device__ float g_k[B_ * LK_ * PROJ_];      // 8192  x 500
__device__ float g_attn[B_ * LQ_ * HEADS];   // 16384 x 10

// ---------------------------------------------------------------------------
// SGEMM v2: C[M,N] = A[M,K] @ W[K,N] + bias[N]
// 128x128 tile, BK=16, 256 threads, 8x8 frags, double-buffered smem,
// float4 global loads with register staging, one sync per stage.
// Requires M % 128 == 0 (true here); N, K fully guarded.
// ---------------------------------------------------------------------------
__global__ __launch_bounds__(256, 2) void sgemm_bias(
    const float* __restrict__ A, const float* __restrict__ W,
    const float* __restrict__ bias, float* __restrict__ C,
    int M, int N, int K)
{
    __shared__ float As[2][16][132];   // [k][m], padded stride
    __shared__ float Bs[2][16][128];   // [k][n]

    const int t  = threadIdx.x;
    const int tx = t & 15;
    const int ty = t >> 4;
    const int m0 = blockIdx.y * 128;
    const int n0 = blockIdx.x * 128;

    // A-tile mapping: 512 float4 (128 rows x 4 f4/row); thread does f = t, t+256
    const int ar0 = t >> 2;              // row 0..63
    const int ac  = (t & 3) * 4;         // col 0,4,8,12
    const int ar1 = ar0 + 64;
    // B-tile mapping: 512 float4 (16 rows x 32 f4/row); thread does f = t, t+256
    const int br0 = t >> 5;              // row 0..7
    const int bc  = (t & 31) * 4;        // col 0..124
    const int br1 = br0 + 8;

    const bool ncols_full = (n0 + 128 <= N);

    float4 ra0, ra1, rb0, rb1;

    auto load_a = [&](int k0, int r) -> float4 {
        const float* p = &A[(size_t)(m0 + r) * K + k0 + ac];
        if (k0 + 16 <= K) return *(const float4*)p;
        float4 v = make_float4(0.f, 0.f, 0.f, 0.f);
        int rem = K - (k0 + ac);
        if (rem >= 4) return *(const float4*)p;
        if (rem >= 1) v.x = p[0];
        if (rem >= 2) v.y = p[1];
        if (rem >= 3) v.z = p[2];
        return v;
    };
    auto load_b = [&](int k0, int r) -> float4 {
        float4 v = make_float4(0.f, 0.f, 0.f, 0.f);
        if (k0 + r < K) {
            const float* p = &W[(size_t)(k0 + r) * N + n0 + bc];
            if (ncols_full || n0 + bc + 3 < N) return *(const float4*)p;
            if (n0 + bc     < N) v.x = p[0];
            if (n0 + bc + 1 < N) v.y = p[1];
            if (n0 + bc + 2 < N) v.z = p[2];
        }
        return v;
    };
    auto fetch = [&](int k0) {
        ra0 = load_a(k0, ar0);
        ra1 = load_a(k0, ar1);
        rb0 = load_b(k0, br0);
        rb1 = load_b(k0, br1);
    };
    auto stage = [&](int buf) {
        As[buf][ac + 0][ar0] = ra0.x;
        As[buf][ac + 1][ar0] = ra0.y;
        As[buf][ac + 2][ar0] = ra0.z;
        As[buf][ac + 3][ar0] = ra0.w;
        As[buf][ac + 0][ar1] = ra1.x;
        As[buf][ac + 1][ar1] = ra1.y;
        As[buf][ac + 2][ar1] = ra1.z;
        As[buf][ac + 3][ar1] = ra1.w;
        *(float4*)&Bs[buf][br0][bc] = rb0;
        *(float4*)&Bs[buf][br1][bc] = rb1;
    };

    float acc[8][8];
#pragma unroll
    for (int i = 0; i < 8; i++)
#pragma unroll
        for (int j = 0; j < 8; j++) acc[i][j] = 0.0f;

    const int ntiles = (K + 15) / 16;

    fetch(0);
    stage(0);
    __syncthreads();

    for (int tl = 0; tl < ntiles; ++tl) {
        const int cur = tl & 1;
        if (tl + 1 < ntiles) fetch((tl + 1) * 16);

#pragma unroll
        for (int kk = 0; kk < 16; kk++) {
            float4 a0 = *(const float4*)&As[cur][kk][ty * 8];
            float4 a1 = *(const float4*)&As[cur][kk][ty * 8 + 4];
            float a[8] = {a0.x, a0.y, a0.z, a0.w, a1.x, a1.y, a1.z, a1.w};
            float b[8];
#pragma unroll
            for (int j = 0; j < 8; j++) b[j] = Bs[cur][kk][tx + 16 * j];
#pragma unroll
            for (int i = 0; i < 8; i++)
#pragma unroll
                for (int j = 0; j < 8; j++) acc[i][j] += a[i] * b[j];
        }

        if (tl + 1 < ntiles) stage(cur ^ 1);
        __syncthreads();
    }

#pragma unroll
    for (int i = 0; i < 8; i++) {
        int m = m0 + ty * 8 + i;
#pragma unroll
        for (int j = 0; j < 8; j++) {
            int n = n0 + tx + 16 * j;
            if (n < N) C[(size_t)m * N + n] = acc[i][j] + bias[n];
        }
    }
}

// ---------------------------------------------------------------------------
// Fused attention: per block (b, h, 128-q tile).
// Streams k in 128-row tiles; per-thread 8x8 score frag; no max-subtraction
// (scores are O(1) for this data), accumulates sum(e*v) and sum(e).
// ---------------------------------------------------------------------------
__global__ __launch_bounds__(256) void attn_kernel(const float* __restrict__ value)
{
    extern __shared__ float sm[];
    float* qs  = sm;            // 6400 floats
    float* ks  = sm + 6400;     // 6400 floats
    float* vsh = sm + 12800;    // 128  floats

    const int b  = blockIdx.z;
    const int h  = blockIdx.y;
    const int q0 = blockIdx.x * 128;
    const int t  = threadIdx.x;
    const int tx = t & 15;
    const int ty = t >> 4;

    for (int idx = t; idx < 128 * HD; idx += 256) {
        int r = idx / HD;
        int c = idx - r * HD;
        qs[idx] = g_q[(size_t)(b * LQ_ + q0 + r) * PROJ_ + h * HD + c];
    }

    float accA[8], accL[8];
#pragma unroll
    for (int i = 0; i < 8; i++) { accA[i] = 0.0f; accL[i] = 0.0f; }

    const float scale = 0.14142135623730951f; // 1/sqrt(50)

    for (int kt = 0; kt < LK_; kt += 128) {
        __syncthreads();
        for (int idx = t; idx < 128 * HD; idx += 256) {
            int r = idx / HD;
            int c = idx - r * HD;
            ks[idx] = g_k[(size_t)(b * LK_ + kt + r) * PROJ_ + h * HD + c];
        }
        if (t < 128) vsh[t] = value[b * LK_ + kt + t];
        __syncthreads();

        float s[8][8];
#pragma unroll
        for (int i = 0; i < 8; i++)
#pragma unroll
            for (int j = 0; j < 8; j++) s[i][j] = 0.0f;

#pragma unroll
        for (int d = 0; d < HD; d += 2) {
            float2 a[8], bb[8];
#pragma unroll
            for (int i = 0; i < 8; i++)
                a[i] = *(const float2*)&qs[(ty * 8 + i) * HD + d];
#pragma unroll
            for (int j = 0; j < 8; j++)
                bb[j] = *(const float2*)&ks[(tx + 16 * j) * HD + d];
#pragma unroll
            for (int i = 0; i < 8; i++)
#pragma unroll
                for (int j = 0; j < 8; j++) {
                    s[i][j] += a[i].x * bb[j].x;
                    s[i][j] += a[i].y * bb[j].y;
                }
        }

#pragma unroll
        for (int j = 0; j < 8; j++) {
            float v = vsh[tx + 16 * j];
#pragma unroll
            for (int i = 0; i < 8; i++) {
                float e = __expf(s[i][j] * scale);
                accA[i] += e * v;
                accL[i] += e;
            }
        }
    }

#pragma unroll
    for (int i = 0; i < 8; i++) {
        float a = accA[i];
        float l = accL[i];
#pragma unroll
        for (int o = 8; o > 0; o >>= 1) {
            a += __shfl_xor_sync(0xffffffffu, a, o);
            l += __shfl_xor_sync(0xffffffffu, l, o);
        }
        if (tx == 0)
            g_attn[(size_t)(b * LQ_ + q0 + ty * 8 + i) * HEADS + h] = a / l;
    }
}

// ---------------------------------------------------------------------------
// Tiny MLP: y = relu(relu(o @ W1 + b1) @ W2 + b2)
// ---------------------------------------------------------------------------
__global__ __launch_bounds__(256) void mlp_kernel(
    const float* __restrict__ W1, const float* __restrict__ b1,
    const float* __restrict__ W2, const float* __restrict__ b2,
    float* __restrict__ out)
{
    int idx = blockIdx.x * blockDim.x + threadIdx.x;
    if (idx >= B_ * LQ_) return;

    float o[HEADS];
#pragma unroll
    for (int i = 0; i < HEADS; i++) o[i] = g_attn[(size_t)idx * HEADS + i];

    float y = b2[0];
#pragma unroll
    for (int j = 0; j < 10; j++) {
        float hj = b1[j];
#pragma unroll
        for (int i = 0; i < HEADS; i++) hj += o[i] * W1[i * 10 + j];
        hj = fmaxf(hj, 0.0f);
        y += hj * W2[j];
    }
    out[idx] = fmaxf(y, 0.0f);
}

// ---------------------------------------------------------------------------
extern "C" void kernel_launch(void* const* d_in, const int* in_sizes, int n_in,
                              void* d_out, int out_size)
{
    const float* query = (const float*)d_in[0];
    const float* key   = (const float*)d_in[1];
    const float* value = (const float*)d_in[2];
    const float* Wq    = (const float*)d_in[3];
    const float* bq    = (const float*)d_in[4];
    const float* Wk    = (const float*)d_in[5];
    const float* bk    = (const float*)d_in[6];
    const float* W1    = (const float*)d_in[7];
    const float* b1    = (const float*)d_in[8];
    const float* W2    = (const float*)d_in[9];
    const float* b2    = (const float*)d_in[10];
    float* out = (float*)d_out;

    float *gq = nullptr, *gk = nullptr;
    cudaGetSymbolAddress((void**)&gq, g_q);
    cudaGetSymbolAddress((void**)&gk, g_k);

    // q projection: [16384,1124] @ [1124,500]
    {
        dim3 grid((PROJ_ + 127) / 128, (B_ * LQ_) / 128);
        sgemm_bias<<<grid, 256>>>(query, Wq, bq, gq, B_ * LQ_, PROJ_, QIN);
    }
    // k projection: [8192,10100] @ [10100,500]
    {
        dim3 grid((PROJ_ + 127) / 128, (B_ * LK_) / 128);
        sgemm_bias<<<grid, 256>>>(key, Wk, bk, gk, B_ * LK_, PROJ_, KIN);
    }
    // fused attention
    {
        const int smem = (128 * HD + 128 * HD + 128) * (int)sizeof(float); // 51,712 B
        cudaFuncSetAttribute(attn_kernel,
                             cudaFuncAttributeMaxDynamicSharedMemorySize, smem);
        dim3 grid(LQ_ / 128, HEADS, B_);
        attn_kernel<<<grid, 256, smem>>>(value);
    }
    // MLP head
    {
        int n = B_ * LQ_;
        mlp_kernel<<<(n + 255) / 256, 256>>>(W1, b1, W2, b2, out);
    }
}